// round 1
// baseline (speedup 1.0000x reference)
#include <cuda_runtime.h>

#define NNODES 50000
#define FDIM 36
#define EMAX 800000

// ---------------- persistent device scratch (no allocs allowed) ----------------
__device__ __align__(16) float g_h[NNODES * FDIM];
__device__ __align__(16) float g_y[NNODES * FDIM];
__device__ __align__(16) float g_als[NNODES * 4];   // padded to float4
__device__ __align__(16) float g_ald[NNODES * 4];
__device__ int g_deg[NNODES];
__device__ int g_cursor[NNODES];
__device__ int g_rowoff[NNODES + 1];
__device__ int g_col[EMAX];

__device__ __forceinline__ float lrelu(float x) { return fmaxf(x, 0.2f * x); }

// ---------------- CSR build ----------------
__global__ void zero_kernel() {
    int i = blockIdx.x * blockDim.x + threadIdx.x;
    if (i < NNODES) { g_deg[i] = 0; g_cursor[i] = 0; }
}

__global__ void count_kernel(const int* __restrict__ dst, int E) {
    int i = blockIdx.x * blockDim.x + threadIdx.x;
    if (i < E) atomicAdd(&g_deg[dst[i]], 1);
}

// single-block exclusive scan over g_deg -> g_rowoff (blockDim must be 1024)
__global__ void scan_kernel() {
    __shared__ int warpsums[32];
    __shared__ int s_carry;
    int tid = threadIdx.x;
    if (tid == 0) s_carry = 0;
    __syncthreads();
    for (int base = 0; base < NNODES; base += 1024) {
        int idx = base + tid;
        int v = (idx < NNODES) ? g_deg[idx] : 0;
        int x = v;
        #pragma unroll
        for (int off = 1; off < 32; off <<= 1) {
            int t = __shfl_up_sync(0xffffffffu, x, off);
            if ((tid & 31) >= off) x += t;
        }
        if ((tid & 31) == 31) warpsums[tid >> 5] = x;
        __syncthreads();
        if (tid < 32) {
            int w = warpsums[tid];
            #pragma unroll
            for (int off = 1; off < 32; off <<= 1) {
                int t = __shfl_up_sync(0xffffffffu, w, off);
                if (tid >= off) w += t;
            }
            warpsums[tid] = w;
        }
        __syncthreads();
        int woff = (tid >= 32) ? warpsums[(tid >> 5) - 1] : 0;
        int incl = x + woff + s_carry;
        if (idx < NNODES) g_rowoff[idx] = incl - v;   // exclusive
        __syncthreads();
        if (tid == 1023) s_carry = incl;
        __syncthreads();
    }
    if (tid == 0) g_rowoff[NNODES] = s_carry;
}

__global__ void scatter_kernel(const int* __restrict__ src, const int* __restrict__ dst, int E) {
    int i = blockIdx.x * blockDim.x + threadIdx.x;
    if (i < E) {
        int d = dst[i];
        int p = atomicAdd(&g_cursor[d], 1);
        g_col[g_rowoff[d] + p] = src[i];
    }
}

// ---------------- per-layer node transform: h = y @ W^T, al_s, al_d ----------------
template <int IN>
__global__ void transform_kernel(const float* __restrict__ yin,
                                 const float* __restrict__ W,
                                 const float* __restrict__ a_src,
                                 const float* __restrict__ a_dst) {
    __shared__ float sW[FDIM * IN];
    __shared__ float sas[FDIM], sad[FDIM];
    int tid = threadIdx.x;
    for (int i = tid; i < FDIM * IN; i += blockDim.x) sW[i] = W[i];
    if (tid < FDIM) { sas[tid] = a_src[tid]; sad[tid] = a_dst[tid]; }
    __syncthreads();
    int n = blockIdx.x * blockDim.x + tid;
    if (n >= NNODES) return;

    const float* yrow = (IN == 24) ? (yin + n * IN) : (g_y + n * IN);
    float yr[IN];
    #pragma unroll
    for (int i = 0; i < IN; i++) yr[i] = yrow[i];

    float als0 = 0, als1 = 0, als2 = 0, ald0 = 0, ald1 = 0, ald2 = 0;
    #pragma unroll
    for (int o = 0; o < FDIM; o++) {
        float acc = 0;
        #pragma unroll
        for (int i = 0; i < IN; i++) acc = fmaf(yr[i], sW[o * IN + i], acc);
        g_h[n * FDIM + o] = acc;
        float as = acc * sas[o], ad = acc * sad[o];
        if (o < 12)      { als0 += as; ald0 += ad; }
        else if (o < 24) { als1 += as; ald1 += ad; }
        else             { als2 += as; ald2 += ad; }
    }
    *(float4*)&g_als[n * 4] = make_float4(als0, als1, als2, 0.f);
    *(float4*)&g_ald[n * 4] = make_float4(ald0, ald1, ald2, 0.f);
}

// ---------------- GAT aggregation (gather by dst, 2-pass softmax) ----------------
__device__ __forceinline__ void gat_aggregate(int n, float acc[FDIM],
                                              float& s0, float& s1, float& s2) {
    int beg = g_rowoff[n], end = g_rowoff[n + 1];
    float4 ad = *(const float4*)&g_ald[n * 4];
    float4 aself = *(const float4*)&g_als[n * 4];
    float e0s = lrelu(aself.x + ad.x);
    float e1s = lrelu(aself.y + ad.y);
    float e2s = lrelu(aself.z + ad.z);
    float m0 = e0s, m1 = e1s, m2 = e2s;

    for (int j = beg; j < end; j++) {
        int sn = g_col[j];
        float4 a = *(const float4*)&g_als[sn * 4];
        m0 = fmaxf(m0, lrelu(a.x + ad.x));
        m1 = fmaxf(m1, lrelu(a.y + ad.y));
        m2 = fmaxf(m2, lrelu(a.z + ad.z));
    }

    float p0 = __expf(e0s - m0), p1 = __expf(e1s - m1), p2 = __expf(e2s - m2);
    s0 = p0; s1 = p1; s2 = p2;
    const float4* hp = (const float4*)(g_h + n * FDIM);
    #pragma unroll
    for (int q = 0; q < 9; q++) {
        float p = (q < 3) ? p0 : ((q < 6) ? p1 : p2);
        float4 v = hp[q];
        acc[4 * q + 0] = p * v.x; acc[4 * q + 1] = p * v.y;
        acc[4 * q + 2] = p * v.z; acc[4 * q + 3] = p * v.w;
    }

    for (int j = beg; j < end; j++) {
        int sn = g_col[j];
        float4 a = *(const float4*)&g_als[sn * 4];
        float q0 = __expf(lrelu(a.x + ad.x) - m0);
        float q1 = __expf(lrelu(a.y + ad.y) - m1);
        float q2 = __expf(lrelu(a.z + ad.z) - m2);
        s0 += q0; s1 += q1; s2 += q2;
        const float4* hq = (const float4*)(g_h + sn * FDIM);
        #pragma unroll
        for (int q = 0; q < 9; q++) {
            float p = (q < 3) ? q0 : ((q < 6) ? q1 : q2);
            float4 v = hq[q];
            acc[4 * q + 0] = fmaf(p, v.x, acc[4 * q + 0]);
            acc[4 * q + 1] = fmaf(p, v.y, acc[4 * q + 1]);
            acc[4 * q + 2] = fmaf(p, v.z, acc[4 * q + 2]);
            acc[4 * q + 3] = fmaf(p, v.w, acc[4 * q + 3]);
        }
    }
}

// layers 0-2: concat + bias + relu -> g_y
__global__ void gather_mid_kernel(const float* __restrict__ bias) {
    __shared__ float sb[FDIM];
    if (threadIdx.x < FDIM) sb[threadIdx.x] = bias[threadIdx.x];
    __syncthreads();
    int n = blockIdx.x * blockDim.x + threadIdx.x;
    if (n >= NNODES) return;
    float acc[FDIM];
    float s0, s1, s2;
    gat_aggregate(n, acc, s0, s1, s2);
    float i0 = 1.f / (s0 + 1e-16f);
    float i1 = 1.f / (s1 + 1e-16f);
    float i2 = 1.f / (s2 + 1e-16f);
    #pragma unroll
    for (int o = 0; o < FDIM; o++) {
        float inv = (o < 12) ? i0 : ((o < 24) ? i1 : i2);
        g_y[n * FDIM + o] = fmaxf(fmaf(acc[o], inv, sb[o]), 0.f);
    }
}

// layer 3: mean over heads + bias, then fused lin1 + lin2 -> d_out
__global__ void gather_last_kernel(const float* __restrict__ b3,
                                   const float* __restrict__ lin1_w,
                                   const float* __restrict__ lin1_b,
                                   const float* __restrict__ lin2_w,
                                   const float* __restrict__ lin2_b,
                                   float* __restrict__ out) {
    __shared__ float sb[12], s1w[144], s1b[12], s2w[72], s2b[6];
    int tid = threadIdx.x;
    if (tid < 12) { sb[tid] = b3[tid]; s1b[tid] = lin1_b[tid]; }
    if (tid < 6) s2b[tid] = lin2_b[tid];
    for (int i = tid; i < 144; i += blockDim.x) s1w[i] = lin1_w[i];
    for (int i = tid; i < 72; i += blockDim.x) s2w[i] = lin2_w[i];
    __syncthreads();
    int n = blockIdx.x * blockDim.x + tid;
    if (n >= NNODES) return;
    float acc[FDIM];
    float s0, s1, s2;
    gat_aggregate(n, acc, s0, s1, s2);
    float i0 = 1.f / (s0 + 1e-16f);
    float i1 = 1.f / (s1 + 1e-16f);
    float i2 = 1.f / (s2 + 1e-16f);

    float o12[12];
    #pragma unroll
    for (int o = 0; o < 12; o++)
        o12[o] = (acc[o] * i0 + acc[12 + o] * i1 + acc[24 + o] * i2) * (1.f / 3.f) + sb[o];

    float t[12];
    #pragma unroll
    for (int j = 0; j < 12; j++) {
        float a = s1b[j];
        #pragma unroll
        for (int k = 0; k < 12; k++) a = fmaf(o12[k], s1w[j * 12 + k], a);
        t[j] = a;
    }
    #pragma unroll
    for (int i = 0; i < 6; i++) {
        float a = s2b[i];
        #pragma unroll
        for (int j = 0; j < 12; j++) a = fmaf(t[j], s2w[i * 12 + j], a);
        out[n * 6 + i] = a;
    }
}

// ---------------- launch ----------------
extern "C" void kernel_launch(void* const* d_in, const int* in_sizes, int n_in,
                              void* d_out, int out_size) {
    const float* x = (const float*)d_in[0];
    const int* ei = (const int*)d_in[1];
    int E = in_sizes[1] / 2;
    const int* src = ei;
    const int* dst = ei + E;

    const float* W[4]   = {(const float*)d_in[2],  (const float*)d_in[6],
                           (const float*)d_in[10], (const float*)d_in[14]};
    const float* asr[4] = {(const float*)d_in[3],  (const float*)d_in[7],
                           (const float*)d_in[11], (const float*)d_in[15]};
    const float* adt[4] = {(const float*)d_in[4],  (const float*)d_in[8],
                           (const float*)d_in[12], (const float*)d_in[16]};
    const float* b[4]   = {(const float*)d_in[5],  (const float*)d_in[9],
                           (const float*)d_in[13], (const float*)d_in[17]};
    const float* lin1_w = (const float*)d_in[18];
    const float* lin1_b = (const float*)d_in[19];
    const float* lin2_w = (const float*)d_in[20];
    const float* lin2_b = (const float*)d_in[21];
    float* out = (float*)d_out;

    int nb = (NNODES + 255) / 256;
    int eb = (E + 255) / 256;
    zero_kernel<<<nb, 256>>>();
    count_kernel<<<eb, 256>>>(dst, E);
    scan_kernel<<<1, 1024>>>();
    scatter_kernel<<<eb, 256>>>(src, dst, E);

    int tb = (NNODES + 127) / 128;
    // layer 0 (in=24, from x)
    transform_kernel<24><<<tb, 128>>>(x, W[0], asr[0], adt[0]);
    gather_mid_kernel<<<tb, 128>>>(b[0]);
    // layers 1,2 (in=36, from g_y)
    transform_kernel<36><<<tb, 128>>>(nullptr, W[1], asr[1], adt[1]);
    gather_mid_kernel<<<tb, 128>>>(b[1]);
    transform_kernel<36><<<tb, 128>>>(nullptr, W[2], asr[2], adt[2]);
    gather_mid_kernel<<<tb, 128>>>(b[2]);
    // layer 3 (in=36, mean heads + lin1 + lin2 fused)
    transform_kernel<36><<<tb, 128>>>(nullptr, W[3], asr[3], adt[3]);
    gather_last_kernel<<<tb, 128>>>(b[3], lin1_w, lin1_b, lin2_w, lin2_b, out);
}

// round 2
// speedup vs baseline: 1.1982x; 1.1982x over previous
#include <cuda_runtime.h>

#define NNODES 50000
#define FDIM 36
#define ROWF 40                 // 36 h + 3 als + 1 pad
#define EMAX 800000

// ---------------- persistent device scratch ----------------
__device__ __align__(16) float g_hpA[NNODES * ROWF];
__device__ __align__(16) float g_hpB[NNODES * ROWF];
__device__ __align__(16) float g_ald[NNODES * 4];
__device__ int g_deg[NNODES];
__device__ int g_rowoff[NNODES + 1];
__device__ int g_rank[EMAX];
__device__ int g_col[EMAX];

__device__ __forceinline__ float lrelu(float x) { return fmaxf(x, 0.2f * x); }

// ---------------- CSR build ----------------
__global__ void zero_kernel() {
    int i = blockIdx.x * blockDim.x + threadIdx.x;
    if (i < NNODES) g_deg[i] = 0;
}

__global__ void count_kernel(const int* __restrict__ dst, int E) {
    int i = blockIdx.x * blockDim.x + threadIdx.x;
    if (i < E) g_rank[i] = atomicAdd(&g_deg[dst[i]], 1);
}

// single-block exclusive scan over g_deg -> g_rowoff
__global__ void scan_kernel() {
    __shared__ int warpsums[32];
    __shared__ int s_carry;
    int tid = threadIdx.x;
    if (tid == 0) s_carry = 0;
    __syncthreads();
    for (int base = 0; base < NNODES; base += 1024) {
        int idx = base + tid;
        int v = (idx < NNODES) ? g_deg[idx] : 0;
        int x = v;
        #pragma unroll
        for (int off = 1; off < 32; off <<= 1) {
            int t = __shfl_up_sync(0xffffffffu, x, off);
            if ((tid & 31) >= off) x += t;
        }
        if ((tid & 31) == 31) warpsums[tid >> 5] = x;
        __syncthreads();
        if (tid < 32) {
            int w = warpsums[tid];
            #pragma unroll
            for (int off = 1; off < 32; off <<= 1) {
                int t = __shfl_up_sync(0xffffffffu, w, off);
                if (tid >= off) w += t;
            }
            warpsums[tid] = w;
        }
        __syncthreads();
        int woff = (tid >= 32) ? warpsums[(tid >> 5) - 1] : 0;
        int incl = x + woff + s_carry;
        if (idx < NNODES) g_rowoff[idx] = incl - v;   // exclusive
        __syncthreads();
        if (tid == 1023) s_carry = incl;
        __syncthreads();
    }
    if (tid == 0) g_rowoff[NNODES] = s_carry;
}

__global__ void scatter_kernel(const int* __restrict__ src, const int* __restrict__ dst, int E) {
    int i = blockIdx.x * blockDim.x + threadIdx.x;
    if (i < E) {
        int d = dst[i];
        g_col[g_rowoff[d] + g_rank[i]] = src[i];
    }
}

// ---------------- layer-0 transform: h = x @ W0^T (in=24) ----------------
__global__ void transform0_kernel(const float* __restrict__ xin,
                                  const float* __restrict__ W,
                                  const float* __restrict__ a_src,
                                  const float* __restrict__ a_dst,
                                  float* __restrict__ hout) {
    __shared__ float sW[FDIM * 24];
    __shared__ float sas[FDIM], sad[FDIM];
    int tid = threadIdx.x;
    for (int i = tid; i < FDIM * 24; i += blockDim.x) sW[i] = W[i];
    if (tid < FDIM) { sas[tid] = a_src[tid]; sad[tid] = a_dst[tid]; }
    __syncthreads();
    int n = blockIdx.x * blockDim.x + tid;
    if (n >= NNODES) return;

    float yr[24];
    const float4* xv = (const float4*)(xin + n * 24);
    #pragma unroll
    for (int q = 0; q < 6; q++) {
        float4 v = xv[q];
        yr[4 * q] = v.x; yr[4 * q + 1] = v.y; yr[4 * q + 2] = v.z; yr[4 * q + 3] = v.w;
    }

    float als0 = 0, als1 = 0, als2 = 0, ald0 = 0, ald1 = 0, ald2 = 0;
    float4* rowv = (float4*)(hout + n * ROWF);
    #pragma unroll
    for (int q = 0; q < 9; q++) {
        float4 hv;
        #pragma unroll
        for (int k = 0; k < 4; k++) {
            int o = q * 4 + k;
            float a = 0;
            #pragma unroll
            for (int i = 0; i < 24; i++) a = fmaf(yr[i], sW[o * 24 + i], a);
            ((float*)&hv)[k] = a;
            float as = a * sas[o], av = a * sad[o];
            if (q < 3)      { als0 += as; ald0 += av; }
            else if (q < 6) { als1 += as; ald1 += av; }
            else            { als2 += as; ald2 += av; }
        }
        rowv[q] = hv;
    }
    rowv[9] = make_float4(als0, als1, als2, 0.f);
    *(float4*)&g_ald[n * 4] = make_float4(ald0, ald1, ald2, 0.f);
}

// ---------------- single-pass aggregation over packed 40-float rows ----------------
__device__ __forceinline__ void aggregate40(int n, const float* __restrict__ hin,
                                            float acc[FDIM],
                                            float& s0, float& s1, float& s2) {
    int beg = g_rowoff[n], end = g_rowoff[n + 1];
    float4 ad = *(const float4*)&g_ald[n * 4];

    // self loop contribution
    const float4* self = (const float4*)(hin + n * ROWF);
    float4 at = self[9];
    float p0 = __expf(lrelu(at.x + ad.x));
    float p1 = __expf(lrelu(at.y + ad.y));
    float p2 = __expf(lrelu(at.z + ad.z));
    s0 = p0; s1 = p1; s2 = p2;
    #pragma unroll
    for (int q = 0; q < 9; q++) {
        float p = (q < 3) ? p0 : ((q < 6) ? p1 : p2);
        float4 v = self[q];
        acc[4 * q + 0] = p * v.x; acc[4 * q + 1] = p * v.y;
        acc[4 * q + 2] = p * v.z; acc[4 * q + 3] = p * v.w;
    }

    for (int j = beg; j < end; j++) {
        int sn = g_col[j];
        const float4* r = (const float4*)(hin + sn * ROWF);
        float4 a = r[9];
        float q0 = __expf(lrelu(a.x + ad.x));
        float q1 = __expf(lrelu(a.y + ad.y));
        float q2 = __expf(lrelu(a.z + ad.z));
        s0 += q0; s1 += q1; s2 += q2;
        #pragma unroll
        for (int q = 0; q < 9; q++) {
            float p = (q < 3) ? q0 : ((q < 6) ? q1 : q2);
            float4 v = r[q];
            acc[4 * q + 0] = fmaf(p, v.x, acc[4 * q + 0]);
            acc[4 * q + 1] = fmaf(p, v.y, acc[4 * q + 1]);
            acc[4 * q + 2] = fmaf(p, v.z, acc[4 * q + 2]);
            acc[4 * q + 3] = fmaf(p, v.w, acc[4 * q + 3]);
        }
    }
}

// layers 0-2: aggregate + relu, then fused next-layer transform -> hout
__global__ void gather_fused_kernel(const float* __restrict__ hin,
                                    float* __restrict__ hout,
                                    const float* __restrict__ bias,
                                    const float* __restrict__ Wn,
                                    const float* __restrict__ a_src,
                                    const float* __restrict__ a_dst) {
    __shared__ float sW[FDIM * FDIM];
    __shared__ float sb[FDIM], sas[FDIM], sad[FDIM];
    int tid = threadIdx.x;
    for (int i = tid; i < FDIM * FDIM; i += blockDim.x) sW[i] = Wn[i];
    if (tid < FDIM) { sb[tid] = bias[tid]; sas[tid] = a_src[tid]; sad[tid] = a_dst[tid]; }
    __syncthreads();
    int n = blockIdx.x * blockDim.x + tid;
    if (n >= NNODES) return;

    float acc[FDIM];
    float s0, s1, s2;
    aggregate40(n, hin, acc, s0, s1, s2);
    float i0 = 1.f / (s0 + 1e-16f);
    float i1 = 1.f / (s1 + 1e-16f);
    float i2 = 1.f / (s2 + 1e-16f);

    float y[FDIM];
    #pragma unroll
    for (int o = 0; o < FDIM; o++) {
        float inv = (o < 12) ? i0 : ((o < 24) ? i1 : i2);
        y[o] = fmaxf(fmaf(acc[o], inv, sb[o]), 0.f);
    }

    // fused next-layer transform
    float als0 = 0, als1 = 0, als2 = 0, ald0 = 0, ald1 = 0, ald2 = 0;
    float4* rowv = (float4*)(hout + n * ROWF);
    #pragma unroll
    for (int q = 0; q < 9; q++) {
        float4 hv;
        #pragma unroll
        for (int k = 0; k < 4; k++) {
            int o = q * 4 + k;
            float a = 0;
            #pragma unroll
            for (int i = 0; i < FDIM; i++) a = fmaf(y[i], sW[o * FDIM + i], a);
            ((float*)&hv)[k] = a;
            float as = a * sas[o], av = a * sad[o];
            if (q < 3)      { als0 += as; ald0 += av; }
            else if (q < 6) { als1 += as; ald1 += av; }
            else            { als2 += as; ald2 += av; }
        }
        rowv[q] = hv;
    }
    rowv[9] = make_float4(als0, als1, als2, 0.f);
    *(float4*)&g_ald[n * 4] = make_float4(ald0, ald1, ald2, 0.f);
}

// layer 3: aggregate + mean over heads + bias + lin1 + lin2 -> out
__global__ void gather_last_kernel(const float* __restrict__ hin,
                                   const float* __restrict__ b3,
                                   const float* __restrict__ lin1_w,
                                   const float* __restrict__ lin1_b,
                                   const float* __restrict__ lin2_w,
                                   const float* __restrict__ lin2_b,
                                   float* __restrict__ out) {
    __shared__ float sb[12], s1w[144], s1b[12], s2w[72], s2b[6];
    int tid = threadIdx.x;
    if (tid < 12) { sb[tid] = b3[tid]; s1b[tid] = lin1_b[tid]; }
    if (tid < 6) s2b[tid] = lin2_b[tid];
    for (int i = tid; i < 144; i += blockDim.x) s1w[i] = lin1_w[i];
    for (int i = tid; i < 72; i += blockDim.x) s2w[i] = lin2_w[i];
    __syncthreads();
    int n = blockIdx.x * blockDim.x + tid;
    if (n >= NNODES) return;

    float acc[FDIM];
    float s0, s1, s2;
    aggregate40(n, hin, acc, s0, s1, s2);
    float i0 = 1.f / (s0 + 1e-16f);
    float i1 = 1.f / (s1 + 1e-16f);
    float i2 = 1.f / (s2 + 1e-16f);

    float o12[12];
    #pragma unroll
    for (int o = 0; o < 12; o++)
        o12[o] = (acc[o] * i0 + acc[12 + o] * i1 + acc[24 + o] * i2) * (1.f / 3.f) + sb[o];

    float t[12];
    #pragma unroll
    for (int j = 0; j < 12; j++) {
        float a = s1b[j];
        #pragma unroll
        for (int k = 0; k < 12; k++) a = fmaf(o12[k], s1w[j * 12 + k], a);
        t[j] = a;
    }
    float2 o01, o23, o45;
    {
        float r[6];
        #pragma unroll
        for (int i = 0; i < 6; i++) {
            float a = s2b[i];
            #pragma unroll
            for (int j = 0; j < 12; j++) a = fmaf(t[j], s2w[i * 12 + j], a);
            r[i] = a;
        }
        o01 = make_float2(r[0], r[1]);
        o23 = make_float2(r[2], r[3]);
        o45 = make_float2(r[4], r[5]);
    }
    float2* ov = (float2*)(out + n * 6);
    ov[0] = o01; ov[1] = o23; ov[2] = o45;
}

// ---------------- launch ----------------
extern "C" void kernel_launch(void* const* d_in, const int* in_sizes, int n_in,
                              void* d_out, int out_size) {
    const float* x = (const float*)d_in[0];
    const int* ei = (const int*)d_in[1];
    int E = in_sizes[1] / 2;
    const int* src = ei;
    const int* dst = ei + E;

    const float* W[4]   = {(const float*)d_in[2],  (const float*)d_in[6],
                           (const float*)d_in[10], (const float*)d_in[14]};
    const float* asr[4] = {(const float*)d_in[3],  (const float*)d_in[7],
                           (const float*)d_in[11], (const float*)d_in[15]};
    const float* adt[4] = {(const float*)d_in[4],  (const float*)d_in[8],
                           (const float*)d_in[12], (const float*)d_in[16]};
    const float* b[4]   = {(const float*)d_in[5],  (const float*)d_in[9],
                           (const float*)d_in[13], (const float*)d_in[17]};
    const float* lin1_w = (const float*)d_in[18];
    const float* lin1_b = (const float*)d_in[19];
    const float* lin2_w = (const float*)d_in[20];
    const float* lin2_b = (const float*)d_in[21];
    float* out = (float*)d_out;

    float* hA; cudaGetSymbolAddress((void**)&hA, g_hpA);
    float* hB; cudaGetSymbolAddress((void**)&hB, g_hpB);

    int nb = (NNODES + 255) / 256;
    int eb = (E + 255) / 256;
    zero_kernel<<<nb, 256>>>();
    count_kernel<<<eb, 256>>>(dst, E);
    scan_kernel<<<1, 1024>>>();
    scatter_kernel<<<eb, 256>>>(src, dst, E);

    int tb = (NNODES + 127) / 128;
    transform0_kernel<<<tb, 128>>>(x, W[0], asr[0], adt[0], hA);
    gather_fused_kernel<<<tb, 128>>>(hA, hB, b[0], W[1], asr[1], adt[1]);
    gather_fused_kernel<<<tb, 128>>>(hB, hA, b[1], W[2], asr[2], adt[2]);
    gather_fused_kernel<<<tb, 128>>>(hA, hB, b[2], W[3], asr[3], adt[3]);
    gather_last_kernel<<<tb, 128>>>(hB, b[3], lin1_w, lin1_b, lin2_w, lin2_b, out);
}

// round 4
// speedup vs baseline: 1.5214x; 1.2698x over previous
#include <cuda_runtime.h>

#define NNODES 50000
#define FDIM 36
#define ROWF 40                 // 36 h + 3 als + 1 pad (floats)
#define EMAX 800000
#define SY_STRIDE 44            // smem y row stride (176B, 16B-multiple)

// ---------------- persistent device scratch ----------------
__device__ __align__(16) float g_hpA[NNODES * ROWF];
__device__ __align__(16) float g_hpB[NNODES * ROWF];
__device__ __align__(16) float g_ald[NNODES * 4];
__device__ int g_deg[NNODES];
__device__ int g_rowstart[NNODES];
__device__ int g_rank[EMAX];
__device__ int g_col[EMAX];
__device__ int g_total;

__device__ __forceinline__ float lrelu(float x) { return fmaxf(x, 0.2f * x); }

// ---------------- CSR build ----------------
__global__ void zero_kernel() {
    int i = blockIdx.x * blockDim.x + threadIdx.x;
    if (i < NNODES) g_deg[i] = 0;
    if (i == 0) g_total = 0;
}

__global__ void count_kernel(const int* __restrict__ dst, int E) {
    int i = blockIdx.x * blockDim.x + threadIdx.x;
    if (i < E) g_rank[i] = atomicAdd(&g_deg[dst[i]], 1);
}

// warp-aggregated segment assignment (row starts unordered; gather is order-independent)
__global__ void assign_kernel() {
    int i = blockIdx.x * blockDim.x + threadIdx.x;
    int lane = threadIdx.x & 31;
    int v = (i < NNODES) ? g_deg[i] : 0;
    int x = v;
    #pragma unroll
    for (int off = 1; off < 32; off <<= 1) {
        int t = __shfl_up_sync(0xffffffffu, x, off);
        if (lane >= off) x += t;
    }
    int wsum = __shfl_sync(0xffffffffu, x, 31);
    int base = 0;
    if (lane == 31) base = atomicAdd(&g_total, wsum);
    base = __shfl_sync(0xffffffffu, base, 31);
    if (i < NNODES) g_rowstart[i] = base + x - v;   // exclusive within warp
}

__global__ void scatter_kernel(const int* __restrict__ src, const int* __restrict__ dst, int E) {
    int i = blockIdx.x * blockDim.x + threadIdx.x;
    if (i < E) {
        int d = dst[i];
        g_col[g_rowstart[d] + g_rank[i]] = src[i];
    }
}

// ---------------- layer-0 transform: h = x @ W0^T (in=24) ----------------
__global__ void transform0_kernel(const float* __restrict__ xin,
                                  const float* __restrict__ W,
                                  const float* __restrict__ a_src,
                                  const float* __restrict__ a_dst,
                                  float* __restrict__ hout) {
    __shared__ float sW[FDIM * 24];
    __shared__ float sas[FDIM], sad[FDIM];
    int tid = threadIdx.x;
    for (int i = tid; i < FDIM * 24; i += blockDim.x) sW[i] = W[i];
    if (tid < FDIM) { sas[tid] = a_src[tid]; sad[tid] = a_dst[tid]; }
    __syncthreads();
    int n = blockIdx.x * blockDim.x + tid;
    if (n >= NNODES) return;

    float yr[24];
    const float4* xv = (const float4*)(xin + n * 24);
    #pragma unroll
    for (int q = 0; q < 6; q++) {
        float4 v = xv[q];
        yr[4 * q] = v.x; yr[4 * q + 1] = v.y; yr[4 * q + 2] = v.z; yr[4 * q + 3] = v.w;
    }

    float als0 = 0, als1 = 0, als2 = 0, ald0 = 0, ald1 = 0, ald2 = 0;
    float4* rowv = (float4*)(hout + n * ROWF);
    #pragma unroll
    for (int q = 0; q < 9; q++) {
        float4 hv;
        #pragma unroll
        for (int k = 0; k < 4; k++) {
            int o = q * 4 + k;
            float a = 0;
            #pragma unroll
            for (int i = 0; i < 24; i++) a = fmaf(yr[i], sW[o * 24 + i], a);
            ((float*)&hv)[k] = a;
            float as = a * sas[o], av = a * sad[o];
            if (q < 3)      { als0 += as; ald0 += av; }
            else if (q < 6) { als1 += as; ald1 += av; }
            else            { als2 += as; ald2 += av; }
        }
        rowv[q] = hv;
    }
    rowv[9] = make_float4(als0, als1, als2, 0.f);
    *(float4*)&g_ald[n * 4] = make_float4(ald0, ald1, ald2, 0.f);
}

// ---------------- 4-lane aggregation core ----------------
// lane lk of node n accumulates quads {lk, lk+4}; lane 0 also quad 8.
__device__ __forceinline__ void aggregate4(int n, int lk, const float* __restrict__ hin,
                                           float4& accA, float4& accB, float4& accC,
                                           float& s0, float& s1, float& s2) {
    int beg = g_rowstart[n];
    int end = beg + g_deg[n];
    float4 ad = *(const float4*)&g_ald[n * 4];

    const float4* self = (const float4*)(hin + n * ROWF);
    float4 at = self[9];
    float p0 = __expf(lrelu(at.x + ad.x));
    float p1 = __expf(lrelu(at.y + ad.y));
    float p2 = __expf(lrelu(at.z + ad.z));
    s0 = p0; s1 = p1; s2 = p2;

    float wA = (lk < 3) ? p0 : p1;
    float wB = (lk < 2) ? p1 : p2;
    {
        float4 vA = self[lk];
        float4 vB = self[lk + 4];
        accA = make_float4(wA * vA.x, wA * vA.y, wA * vA.z, wA * vA.w);
        accB = make_float4(wB * vB.x, wB * vB.y, wB * vB.z, wB * vB.w);
        if (lk == 0) {
            float4 vC = self[8];
            accC = make_float4(p2 * vC.x, p2 * vC.y, p2 * vC.z, p2 * vC.w);
        } else {
            accC = make_float4(0.f, 0.f, 0.f, 0.f);
        }
    }

    for (int j = beg; j < end; j++) {
        int sn = g_col[j];
        const float4* r = (const float4*)(hin + sn * ROWF);
        float4 a = r[9];
        float4 vA = r[lk];
        float4 vB = r[lk + 4];
        float q0 = __expf(lrelu(a.x + ad.x));
        float q1 = __expf(lrelu(a.y + ad.y));
        float q2 = __expf(lrelu(a.z + ad.z));
        s0 += q0; s1 += q1; s2 += q2;
        float uA = (lk < 3) ? q0 : q1;
        float uB = (lk < 2) ? q1 : q2;
        accA.x = fmaf(uA, vA.x, accA.x); accA.y = fmaf(uA, vA.y, accA.y);
        accA.z = fmaf(uA, vA.z, accA.z); accA.w = fmaf(uA, vA.w, accA.w);
        accB.x = fmaf(uB, vB.x, accB.x); accB.y = fmaf(uB, vB.y, accB.y);
        accB.z = fmaf(uB, vB.z, accB.z); accB.w = fmaf(uB, vB.w, accB.w);
        if (lk == 0) {
            float4 vC = r[8];
            accC.x = fmaf(q2, vC.x, accC.x); accC.y = fmaf(q2, vC.y, accC.y);
            accC.z = fmaf(q2, vC.z, accC.z); accC.w = fmaf(q2, vC.w, accC.w);
        }
    }
}

// layers 0-2: aggregate + relu + fused next-layer transform -> hout
__global__ void gather_fused_kernel(const float* __restrict__ hin,
                                    float* __restrict__ hout,
                                    const float* __restrict__ bias,
                                    const float* __restrict__ Wn,
                                    const float* __restrict__ a_src,
                                    const float* __restrict__ a_dst) {
    __shared__ __align__(16) float sy[64 * SY_STRIDE];
    __shared__ float sW[FDIM * FDIM];
    __shared__ float sb[FDIM], sas[FDIM], sad[FDIM];
    int tid = threadIdx.x;
    for (int i = tid; i < FDIM * FDIM; i += blockDim.x) sW[i] = Wn[i];
    if (tid < FDIM) { sb[tid] = bias[tid]; sas[tid] = a_src[tid]; sad[tid] = a_dst[tid]; }
    __syncthreads();

    int t = blockIdx.x * blockDim.x + tid;
    int n = t >> 2;
    int lk = t & 3;
    if (n >= NNODES) return;
    int nl = tid >> 2;                 // node-local index in block (0..63)
    float* yrow = &sy[nl * SY_STRIDE];

    float4 accA, accB, accC;
    float s0, s1, s2;
    aggregate4(n, lk, hin, accA, accB, accC, s0, s1, s2);

    float i0 = 1.f / (s0 + 1e-16f);
    float i1 = 1.f / (s1 + 1e-16f);
    float i2 = 1.f / (s2 + 1e-16f);
    float invA = (lk < 3) ? i0 : i1;
    float invB = (lk < 2) ? i1 : i2;

    // normalized + bias + relu -> shared
    {
        int oA = 4 * lk, oB = 16 + 4 * lk;
        float4 yA = make_float4(fmaxf(fmaf(accA.x, invA, sb[oA + 0]), 0.f),
                                fmaxf(fmaf(accA.y, invA, sb[oA + 1]), 0.f),
                                fmaxf(fmaf(accA.z, invA, sb[oA + 2]), 0.f),
                                fmaxf(fmaf(accA.w, invA, sb[oA + 3]), 0.f));
        float4 yB = make_float4(fmaxf(fmaf(accB.x, invB, sb[oB + 0]), 0.f),
                                fmaxf(fmaf(accB.y, invB, sb[oB + 1]), 0.f),
                                fmaxf(fmaf(accB.z, invB, sb[oB + 2]), 0.f),
                                fmaxf(fmaf(accB.w, invB, sb[oB + 3]), 0.f));
        *(float4*)&yrow[oA] = yA;
        *(float4*)&yrow[oB] = yB;
        if (lk == 0) {
            float4 yC = make_float4(fmaxf(fmaf(accC.x, i2, sb[32]), 0.f),
                                    fmaxf(fmaf(accC.y, i2, sb[33]), 0.f),
                                    fmaxf(fmaf(accC.z, i2, sb[34]), 0.f),
                                    fmaxf(fmaf(accC.w, i2, sb[35]), 0.f));
            *(float4*)&yrow[32] = yC;
        }
    }
    __syncwarp();

    // read full y
    float yv[36];
    #pragma unroll
    for (int q = 0; q < 9; q++) {
        float4 v = *(const float4*)&yrow[4 * q];
        yv[4 * q] = v.x; yv[4 * q + 1] = v.y; yv[4 * q + 2] = v.z; yv[4 * q + 3] = v.w;
    }

    // next-layer transform: lane computes quads {lk, lk+4}, lane0 also quad 8
    float pls0 = 0, pls1 = 0, pls2 = 0, pld0 = 0, pld1 = 0, pld2 = 0;
    float4* rowv = (float4*)(hout + n * ROWF);
    {
        float4 hA, hB, hC;
        #pragma unroll
        for (int k = 0; k < 4; k++) {
            int o = 4 * lk + k;
            float a = 0;
            #pragma unroll
            for (int i = 0; i < FDIM; i++) a = fmaf(yv[i], sW[o * FDIM + i], a);
            ((float*)&hA)[k] = a;
            float as = a * sas[o], av = a * sad[o];
            pls0 += as; pld0 += av;   // quad lk: head0 for lk<3, head1 for lk==3 (moved below)
        }
        if (lk == 3) { pls1 = pls0; pld1 = pld0; pls0 = 0; pld0 = 0; }
        float qls = 0, qld = 0;
        #pragma unroll
        for (int k = 0; k < 4; k++) {
            int o = 16 + 4 * lk + k;
            float a = 0;
            #pragma unroll
            for (int i = 0; i < FDIM; i++) a = fmaf(yv[i], sW[o * FDIM + i], a);
            ((float*)&hB)[k] = a;
            qls += a * sas[o]; qld += a * sad[o];
        }
        if (lk < 2) { pls1 += qls; pld1 += qld; } else { pls2 += qls; pld2 += qld; }
        rowv[lk] = hA;
        rowv[lk + 4] = hB;
        if (lk == 0) {
            #pragma unroll
            for (int k = 0; k < 4; k++) {
                int o = 32 + k;
                float a = 0;
                #pragma unroll
                for (int i = 0; i < FDIM; i++) a = fmaf(yv[i], sW[o * FDIM + i], a);
                ((float*)&hC)[k] = a;
                pls2 += a * sas[o]; pld2 += a * sad[o];
            }
            rowv[8] = hC;
        }
    }
    // reduce als/ald partials across the 4-lane group
    #pragma unroll
    for (int off = 1; off < 4; off <<= 1) {
        pls0 += __shfl_xor_sync(0xffffffffu, pls0, off);
        pls1 += __shfl_xor_sync(0xffffffffu, pls1, off);
        pls2 += __shfl_xor_sync(0xffffffffu, pls2, off);
        pld0 += __shfl_xor_sync(0xffffffffu, pld0, off);
        pld1 += __shfl_xor_sync(0xffffffffu, pld1, off);
        pld2 += __shfl_xor_sync(0xffffffffu, pld2, off);
    }
    if (lk == 0) {
        rowv[9] = make_float4(pls0, pls1, pls2, 0.f);
        *(float4*)&g_ald[n * 4] = make_float4(pld0, pld1, pld2, 0.f);
    }
}

// layer 3: aggregate + head-mean + bias + lin1 + lin2 -> out
__global__ void gather_last_kernel(const float* __restrict__ hin,
                                   const float* __restrict__ b3,
                                   const float* __restrict__ lin1_w,
                                   const float* __restrict__ lin1_b,
                                   const float* __restrict__ lin2_w,
                                   const float* __restrict__ lin2_b,
                                   float* __restrict__ out) {
    __shared__ __align__(16) float sy[64 * SY_STRIDE];
    __shared__ float sb[12], s1w[144], s1b[12], s2w[72], s2b[6];
    int tid = threadIdx.x;
    if (tid < 12) { sb[tid] = b3[tid]; s1b[tid] = lin1_b[tid]; }
    if (tid < 6) s2b[tid] = lin2_b[tid];
    for (int i = tid; i < 144; i += blockDim.x) s1w[i] = lin1_w[i];
    for (int i = tid; i < 72; i += blockDim.x) s2w[i] = lin2_w[i];
    __syncthreads();

    int t = blockIdx.x * blockDim.x + tid;
    int n = t >> 2;
    int lk = t & 3;
    if (n >= NNODES) return;
    int nl = tid >> 2;
    float* yrow = &sy[nl * SY_STRIDE];

    float4 accA, accB, accC;
    float s0, s1, s2;
    aggregate4(n, lk, hin, accA, accB, accC, s0, s1, s2);

    float i0 = 1.f / (s0 + 1e-16f);
    float i1 = 1.f / (s1 + 1e-16f);
    float i2 = 1.f / (s2 + 1e-16f);
    float invA = (lk < 3) ? i0 : i1;
    float invB = (lk < 2) ? i1 : i2;

    *(float4*)&yrow[4 * lk] = make_float4(accA.x * invA, accA.y * invA, accA.z * invA, accA.w * invA);
    *(float4*)&yrow[16 + 4 * lk] = make_float4(accB.x * invB, accB.y * invB, accB.z * invB, accB.w * invB);
    if (lk == 0)
        *(float4*)&yrow[32] = make_float4(accC.x * i2, accC.y * i2, accC.z * i2, accC.w * i2);
    __syncwarp();

    if (lk == 0) {
        float o12[12];
        #pragma unroll
        for (int o = 0; o < 12; o++)
            o12[o] = (yrow[o] + yrow[o + 12] + yrow[o + 24]) * (1.f / 3.f) + sb[o];
        float tt[12];
        #pragma unroll
        for (int j = 0; j < 12; j++) {
            float a = s1b[j];
            #pragma unroll
            for (int k = 0; k < 12; k++) a = fmaf(o12[k], s1w[j * 12 + k], a);
            tt[j] = a;
        }
        float r[6];
        #pragma unroll
        for (int i = 0; i < 6; i++) {
            float a = s2b[i];
            #pragma unroll
            for (int j = 0; j < 12; j++) a = fmaf(tt[j], s2w[i * 12 + j], a);
            r[i] = a;
        }
        float2* ov = (float2*)(out + n * 6);
        ov[0] = make_float2(r[0], r[1]);
        ov[1] = make_float2(r[2], r[3]);
        ov[2] = make_float2(r[4], r[5]);
    }
}

// ---------------- launch ----------------
extern "C" void kernel_launch(void* const* d_in, const int* in_sizes, int n_in,
                              void* d_out, int out_size) {
    const float* x = (const float*)d_in[0];
    const int* ei = (const int*)d_in[1];
    int E = in_sizes[1] / 2;
    const int* src = ei;
    const int* dst = ei + E;

    const float* W[4]   = {(const float*)d_in[2],  (const float*)d_in[6],
                           (const float*)d_in[10], (const float*)d_in[14]};
    const float* asr[4] = {(const float*)d_in[3],  (const float*)d_in[7],
                           (const float*)d_in[11], (const float*)d_in[15]};
    const float* adt[4] = {(const float*)d_in[4],  (const float*)d_in[8],
                           (const float*)d_in[12], (const float*)d_in[16]};
    const float* b[4]   = {(const float*)d_in[5],  (const float*)d_in[9],
                           (const float*)d_in[13], (const float*)d_in[17]};
    const float* lin1_w = (const float*)d_in[18];
    const float* lin1_b = (const float*)d_in[19];
    const float* lin2_w = (const float*)d_in[20];
    const float* lin2_b = (const float*)d_in[21];
    float* out = (float*)d_out;

    float* hA; cudaGetSymbolAddress((void**)&hA, g_hpA);
    float* hB; cudaGetSymbolAddress((void**)&hB, g_hpB);

    int nb = (NNODES + 255) / 256;
    int eb = (E + 255) / 256;
    zero_kernel<<<nb, 256>>>();
    count_kernel<<<eb, 256>>>(dst, E);
    assign_kernel<<<nb, 256>>>();
    scatter_kernel<<<eb, 256>>>(src, dst, E);

    transform0_kernel<<<(NNODES + 255) / 256, 256>>>(x, W[0], asr[0], adt[0], hA);

    int gb = (NNODES * 4 + 255) / 256;
    gather_fused_kernel<<<gb, 256>>>(hA, hB, b[0], W[1], asr[1], adt[1]);
    gather_fused_kernel<<<gb, 256>>>(hB, hA, b[1], W[2], asr[2], adt[2]);
    gather_fused_kernel<<<gb, 256>>>(hA, hB, b[2], W[3], asr[3], adt[3]);
    gather_last_kernel<<<gb, 256>>>(hB, b[3], lin1_w, lin1_b, lin2_w, lin2_b, out);
}